// round 1
// baseline (speedup 1.0000x reference)
#include <cuda_runtime.h>
#include <cuda_bf16.h>
#include <cstdint>

#define NSMP  8192
#define NAX   512
#define DOUTC 256
#define NCOLS 8712   /* REALNA + NSMP */
#define AOFF  512    /* A starts at col 512 of input */
#define OUTS  8448   /* output row stride */
#define ST    40     /* smem row stride in bf16 elements (conflict-free, 16B-store friendly) */

#define SMEMB ((2*64*ST + 2*256*ST) * 2)   /* 51200 bytes */

// ---------------- scratch globals (no allocation allowed) ----------------
__device__ float          g_part[8 * NSMP];          // partial column sums
__device__ float          g_dis[NSMP];               // d^-1/2
__device__ float          g_Spf[NSMP * DOUTC];       // S' fp32, [j][c]
__device__ __nv_bfloat16  g_SpT[DOUTC * NSMP];       // S' bf16, transposed [c][j]
__device__ __nv_bfloat16  g_WT[DOUTC * NAX];         // weight bf16, transposed [c][k]

// ---------------- helpers ----------------
__device__ __forceinline__ uint32_t pk_bf2(float a, float b) {
    __nv_bfloat162 h = __floats2bfloat162_rn(a, b);
    return *reinterpret_cast<uint32_t*>(&h);
}

__device__ __forceinline__ void mma16816(float* c,
    uint32_t a0, uint32_t a1, uint32_t a2, uint32_t a3,
    uint32_t b0, uint32_t b1)
{
    asm volatile(
        "mma.sync.aligned.m16n8k16.row.col.f32.bf16.bf16.f32 "
        "{%0,%1,%2,%3},{%4,%5,%6,%7},{%8,%9},{%0,%1,%2,%3};\n"
        : "+f"(c[0]), "+f"(c[1]), "+f"(c[2]), "+f"(c[3])
        : "r"(a0), "r"(a1), "r"(a2), "r"(a3), "r"(b0), "r"(b1));
}

// ---------------- kernel 1: partial column sums of A ----------------
__global__ void k_colsum(const float* __restrict__ in) {
    int j  = blockIdx.x * 256 + threadIdx.x;       // column 0..8191
    int r0 = blockIdx.y * 1024;                    // row chunk
    const float* p = in + (size_t)r0 * NCOLS + AOFF + j;
    float s0 = 0.f, s1 = 0.f, s2 = 0.f, s3 = 0.f;
    for (int r = 0; r < 1024; r += 4) {
        s0 += p[0];
        s1 += p[(size_t)NCOLS];
        s2 += p[(size_t)2 * NCOLS];
        s3 += p[(size_t)3 * NCOLS];
        p  += (size_t)4 * NCOLS;
    }
    g_part[blockIdx.y * NSMP + j] = (s0 + s1) + (s2 + s3);
}

// ---------------- kernel 1b: d^-1/2 ----------------
__global__ void k_dis() {
    int j = blockIdx.x * 256 + threadIdx.x;
    float s = 1.0f;  // identity contribution
#pragma unroll
    for (int b = 0; b < 8; b++) s += g_part[b * NSMP + j];
    g_dis[j] = rsqrtf(s);
}

// ---------------- kernel 0b: transpose+convert weight ----------------
__global__ void k_wt(const float* __restrict__ w) {
    int i = blockIdx.x * 256 + threadIdx.x;  // i = k*256 + c
    if (i < NAX * DOUTC) {
        int k = i / DOUTC, c = i % DOUTC;
        g_WT[c * NAX + k] = __float2bfloat16(w[i]);
    }
}

// ---------------- kernel 2: S' = dis ⊙ (X @ W), bf16 MMA ----------------
__global__ void __launch_bounds__(256, 1) k_support(const float* __restrict__ in) {
    extern __shared__ __nv_bfloat16 sh[];
    __nv_bfloat16* sA = sh;               // 2 bufs x 64*ST
    __nv_bfloat16* sB = sh + 2 * 64 * ST; // 2 bufs x 256*ST

    const int t    = threadIdx.x;
    const int row0 = blockIdx.x * 64;
    const int warp = t >> 5, lane = t & 31;
    const int wm = warp & 3, wn = warp >> 2;
    const int g  = lane >> 2, tq = lane & 3;
    const int lr = t >> 2, lc = (t & 3) * 8;

    float acc[16][4];
#pragma unroll
    for (int f = 0; f < 16; f++) { acc[f][0]=acc[f][1]=acc[f][2]=acc[f][3]=0.f; }

    const float* gA = in + (size_t)(row0 + lr) * NCOLS + lc;   // X
    const __nv_bfloat16* gB = g_WT + (size_t)t * NAX;

    float4 ra0, ra1; uint4 rb0, rb1, rb2, rb3;
    ra0 = *(const float4*)(gA);
    ra1 = *(const float4*)(gA + 4);
    rb0 = *(const uint4*)(gB);
    rb1 = *(const uint4*)(gB + 8);
    rb2 = *(const uint4*)(gB + 16);
    rb3 = *(const uint4*)(gB + 24);

    const int NKT = NAX / 32;
    for (int kt = 0; kt < NKT; ++kt) {
        __nv_bfloat16* a_s = sA + (kt & 1) * 64 * ST;
        __nv_bfloat16* b_s = sB + (kt & 1) * 256 * ST;
        uint4 ap;
        ap.x = pk_bf2(ra0.x, ra0.y); ap.y = pk_bf2(ra0.z, ra0.w);
        ap.z = pk_bf2(ra1.x, ra1.y); ap.w = pk_bf2(ra1.z, ra1.w);
        *(uint4*)(a_s + lr * ST + lc) = ap;
        *(uint4*)(b_s + t * ST +  0) = rb0;
        *(uint4*)(b_s + t * ST +  8) = rb1;
        *(uint4*)(b_s + t * ST + 16) = rb2;
        *(uint4*)(b_s + t * ST + 24) = rb3;
        __syncthreads();
        if (kt + 1 < NKT) {
            int kn = (kt + 1) * 32;
            ra0 = *(const float4*)(gA + kn);
            ra1 = *(const float4*)(gA + kn + 4);
            rb0 = *(const uint4*)(gB + kn);
            rb1 = *(const uint4*)(gB + kn + 8);
            rb2 = *(const uint4*)(gB + kn + 16);
            rb3 = *(const uint4*)(gB + kn + 24);
        }
#pragma unroll
        for (int ks = 0; ks < 2; ks++) {
            int kb = ks * 16 + 2 * tq;
            uint32_t a0 = *(const uint32_t*)(a_s + (wm*16 + g    ) * ST + kb);
            uint32_t a1 = *(const uint32_t*)(a_s + (wm*16 + g + 8) * ST + kb);
            uint32_t a2 = *(const uint32_t*)(a_s + (wm*16 + g    ) * ST + kb + 8);
            uint32_t a3 = *(const uint32_t*)(a_s + (wm*16 + g + 8) * ST + kb + 8);
#pragma unroll
            for (int f = 0; f < 16; f++) {
                int n0 = wn * 128 + f * 8;
                uint32_t b0 = *(const uint32_t*)(b_s + (n0 + g) * ST + kb);
                uint32_t b1 = *(const uint32_t*)(b_s + (n0 + g) * ST + kb + 8);
                mma16816(acc[f], a0, a1, a2, a3, b0, b1);
            }
        }
        __syncthreads();
    }

    // epilogue: scale by dis[j], write fp32 [j][c] and bf16 transposed [c][j]
    int r1 = row0 + wm * 16 + g;
    int r2 = r1 + 8;
    float d1 = g_dis[r1], d2 = g_dis[r2];
#pragma unroll
    for (int f = 0; f < 16; f++) {
        int c = wn * 128 + f * 8 + 2 * tq;
        float sp0 = acc[f][0] * d1, sp1 = acc[f][1] * d1;
        float sp2 = acc[f][2] * d2, sp3 = acc[f][3] * d2;
        *(float2*)(g_Spf + (size_t)r1 * DOUTC + c) = make_float2(sp0, sp1);
        *(float2*)(g_Spf + (size_t)r2 * DOUTC + c) = make_float2(sp2, sp3);
        g_SpT[(size_t)(c    ) * NSMP + r1] = __float2bfloat16(sp0);
        g_SpT[(size_t)(c + 1) * NSMP + r1] = __float2bfloat16(sp1);
        g_SpT[(size_t)(c    ) * NSMP + r2] = __float2bfloat16(sp2);
        g_SpT[(size_t)(c + 1) * NSMP + r2] = __float2bfloat16(sp3);
    }
}

// ---------------- kernel 3: out[:,0:256] = dis ⊙ (A_eff @ S'); out[:,256:] = A_eff
__global__ void __launch_bounds__(256, 1) k_main(const float* __restrict__ in,
                                                 float* __restrict__ out) {
    extern __shared__ __nv_bfloat16 sh[];
    __nv_bfloat16* sA = sh;
    __nv_bfloat16* sB = sh + 2 * 64 * ST;

    const int t    = threadIdx.x;
    const int row0 = blockIdx.x * 64;
    const int warp = t >> 5, lane = t & 31;
    const int wm = warp & 3, wn = warp >> 2;
    const int g  = lane >> 2, tq = lane & 3;
    const int lr = t >> 2, lc = (t & 3) * 8;

    float acc[16][4];
#pragma unroll
    for (int f = 0; f < 16; f++) { acc[f][0]=acc[f][1]=acc[f][2]=acc[f][3]=0.f; }

    const float* gA = in + (size_t)(row0 + lr) * NCOLS + AOFF + lc;
    const __nv_bfloat16* gB = g_SpT + (size_t)t * NSMP;
    float* gO = out + (size_t)(row0 + lr) * OUTS + 256 + lc;
    const int grow = row0 + lr;

    float4 ra0, ra1; uint4 rb0, rb1, rb2, rb3;
    ra0 = *(const float4*)(gA);
    ra1 = *(const float4*)(gA + 4);
    rb0 = *(const uint4*)(gB);
    rb1 = *(const uint4*)(gB + 8);
    rb2 = *(const uint4*)(gB + 16);
    rb3 = *(const uint4*)(gB + 24);

    const int NKT = NSMP / 32;
    for (int kt = 0; kt < NKT; ++kt) {
        int k0 = kt * 32;
        // fused copy of A (+1 on diagonal) into out[:,256:]
        float v[8] = {ra0.x, ra0.y, ra0.z, ra0.w, ra1.x, ra1.y, ra1.z, ra1.w};
        int dd = grow - (k0 + lc);
        float vo[8];
#pragma unroll
        for (int i2 = 0; i2 < 8; i2++) vo[i2] = v[i2] + ((dd == i2) ? 1.0f : 0.0f);
        *(float4*)(gO + k0)     = make_float4(vo[0], vo[1], vo[2], vo[3]);
        *(float4*)(gO + k0 + 4) = make_float4(vo[4], vo[5], vo[6], vo[7]);

        // stage (raw A, identity handled via +S'[i] in epilogue)
        __nv_bfloat16* a_s = sA + (kt & 1) * 64 * ST;
        __nv_bfloat16* b_s = sB + (kt & 1) * 256 * ST;
        uint4 ap;
        ap.x = pk_bf2(v[0], v[1]); ap.y = pk_bf2(v[2], v[3]);
        ap.z = pk_bf2(v[4], v[5]); ap.w = pk_bf2(v[6], v[7]);
        *(uint4*)(a_s + lr * ST + lc) = ap;
        *(uint4*)(b_s + t * ST +  0) = rb0;
        *(uint4*)(b_s + t * ST +  8) = rb1;
        *(uint4*)(b_s + t * ST + 16) = rb2;
        *(uint4*)(b_s + t * ST + 24) = rb3;
        __syncthreads();

        if (kt + 1 < NKT) {
            int kn = k0 + 32;
            ra0 = *(const float4*)(gA + kn);
            ra1 = *(const float4*)(gA + kn + 4);
            rb0 = *(const uint4*)(gB + kn);
            rb1 = *(const uint4*)(gB + kn + 8);
            rb2 = *(const uint4*)(gB + kn + 16);
            rb3 = *(const uint4*)(gB + kn + 24);
        }

#pragma unroll
        for (int ks = 0; ks < 2; ks++) {
            int kb = ks * 16 + 2 * tq;
            uint32_t a0 = *(const uint32_t*)(a_s + (wm*16 + g    ) * ST + kb);
            uint32_t a1 = *(const uint32_t*)(a_s + (wm*16 + g + 8) * ST + kb);
            uint32_t a2 = *(const uint32_t*)(a_s + (wm*16 + g    ) * ST + kb + 8);
            uint32_t a3 = *(const uint32_t*)(a_s + (wm*16 + g + 8) * ST + kb + 8);
#pragma unroll
            for (int f = 0; f < 16; f++) {
                int n0 = wn * 128 + f * 8;
                uint32_t b0 = *(const uint32_t*)(b_s + (n0 + g) * ST + kb);
                uint32_t b1 = *(const uint32_t*)(b_s + (n0 + g) * ST + kb + 8);
                mma16816(acc[f], a0, a1, a2, a3, b0, b1);
            }
        }
        __syncthreads();
    }

    // epilogue: out[i,c] = dis[i] * (acc + S'[i,c])   (the +S' is the identity diagonal)
    int r1 = row0 + wm * 16 + g;
    int r2 = r1 + 8;
    float d1 = g_dis[r1], d2 = g_dis[r2];
#pragma unroll
    for (int f = 0; f < 16; f++) {
        int c = wn * 128 + f * 8 + 2 * tq;
        float2 s1 = *(const float2*)(g_Spf + (size_t)r1 * DOUTC + c);
        float2 s2 = *(const float2*)(g_Spf + (size_t)r2 * DOUTC + c);
        *(float2*)(out + (size_t)r1 * OUTS + c) =
            make_float2((acc[f][0] + s1.x) * d1, (acc[f][1] + s1.y) * d1);
        *(float2*)(out + (size_t)r2 * OUTS + c) =
            make_float2((acc[f][2] + s2.x) * d2, (acc[f][3] + s2.y) * d2);
    }
}

// ---------------- launch ----------------
extern "C" void kernel_launch(void* const* d_in, const int* in_sizes, int n_in,
                              void* d_out, int out_size) {
    const float* in = (const float*)d_in[0];
    const float* w  = (const float*)d_in[1];
    float* out = (float*)d_out;

    cudaFuncSetAttribute(k_support, cudaFuncAttributeMaxDynamicSharedMemorySize, SMEMB);
    cudaFuncSetAttribute(k_main,    cudaFuncAttributeMaxDynamicSharedMemorySize, SMEMB);

    k_colsum<<<dim3(32, 8), 256>>>(in);
    k_dis<<<32, 256>>>();
    k_wt<<<(NAX * DOUTC + 255) / 256, 256>>>(w);
    k_support<<<NSMP / 64, 256, SMEMB>>>(in);
    k_main<<<NSMP / 64, 256, SMEMB>>>(in, out);
}

// round 2
// speedup vs baseline: 1.7683x; 1.7683x over previous
#include <cuda_runtime.h>
#include <cuda_bf16.h>
#include <cstdint>

#define NSMP  8192
#define NAX   512
#define DOUTC 256
#define NCOLS 8712   /* REALNA + NSMP */
#define AOFF  512    /* A starts at col 512 of input */
#define OUTS  8448   /* output row stride */

/* ---- k_support tiling (unchanged mainloop) ---- */
#define ST    40
#define SMEM_SUP ((2*64*ST + 2*256*ST) * 2)   /* 51200 B; transpose buf 256*72*2=36864 fits */

/* ---- k_main tiling ---- */
#define KT      64                 /* K per stage */
#define STAGES  3
#define AST     72                 /* padded smem row stride (elems); 144B = 16B-aligned, LDSM conflict-free */
#define A_STAGE (64*AST)           /* elems */
#define B_STAGE (256*AST)
#define STAGE_E (A_STAGE + B_STAGE)
#define SMEM_MAIN (STAGES*STAGE_E*2)   /* 138240 B */

/* ---------------- scratch globals ---------------- */
__device__ float          g_part[16 * NSMP];
__device__ float          g_dis[NSMP];
__device__ float          g_Spf[NSMP * DOUTC];          /* S' fp32, [j][c] */
__device__ __nv_bfloat16  g_SpT[DOUTC * NSMP];          /* S' bf16, [c][j] (K-major for GEMM B) */
__device__ __nv_bfloat16  g_WT[DOUTC * NAX];            /* weight bf16, [c][k] */
__device__ __nv_bfloat16  g_Abf[(size_t)NSMP * NSMP];   /* A bf16 (raw, no +I), row-major */

/* ---------------- helpers ---------------- */
__device__ __forceinline__ uint32_t pk_bf2(float a, float b) {
    __nv_bfloat162 h = __floats2bfloat162_rn(a, b);
    return *reinterpret_cast<uint32_t*>(&h);
}

__device__ __forceinline__ void mma16816(float* c,
    uint32_t a0, uint32_t a1, uint32_t a2, uint32_t a3,
    uint32_t b0, uint32_t b1)
{
    asm volatile(
        "mma.sync.aligned.m16n8k16.row.col.f32.bf16.bf16.f32 "
        "{%0,%1,%2,%3},{%4,%5,%6,%7},{%8,%9},{%0,%1,%2,%3};\n"
        : "+f"(c[0]), "+f"(c[1]), "+f"(c[2]), "+f"(c[3])
        : "r"(a0), "r"(a1), "r"(a2), "r"(a3), "r"(b0), "r"(b1));
}

__device__ __forceinline__ void ldsm4(uint32_t& r0, uint32_t& r1, uint32_t& r2, uint32_t& r3,
                                      uint32_t saddr) {
    asm volatile("ldmatrix.sync.aligned.m8n8.x4.shared.b16 {%0,%1,%2,%3},[%4];\n"
                 : "=r"(r0), "=r"(r1), "=r"(r2), "=r"(r3) : "r"(saddr));
}

__device__ __forceinline__ void cpa16(uint32_t saddr, const void* g) {
    asm volatile("cp.async.cg.shared.global [%0],[%1],16;\n" :: "r"(saddr), "l"(g));
}

/* ---------------- kernel P: fused colsum + A copy(+I) + bf16 convert ---------------- */
__global__ void k_prep(const float* __restrict__ in, float* __restrict__ out) {
    int j  = blockIdx.x * 256 + threadIdx.x;   /* column 0..8191 */
    int r0 = blockIdx.y * 512;                 /* row chunk */
    const float* p = in + (size_t)r0 * NCOLS + AOFF + j;
    float* po = out + (size_t)r0 * OUTS + 256 + j;
    __nv_bfloat16* pb = g_Abf + (size_t)r0 * NSMP + j;
    float s = 0.f;
#pragma unroll 4
    for (int r = 0; r < 512; r++) {
        float v = p[0];
        s += v;
        po[0] = v + ((r0 + r == j) ? 1.0f : 0.0f);
        pb[0] = __float2bfloat16(v);
        p  += NCOLS; po += OUTS; pb += NSMP;
    }
    g_part[blockIdx.y * NSMP + j] = s;
}

/* ---------------- kernel 1b: d^-1/2 ---------------- */
__global__ void k_dis() {
    int j = blockIdx.x * 256 + threadIdx.x;
    float s = 1.0f;  /* identity contribution */
#pragma unroll
    for (int b = 0; b < 16; b++) s += g_part[b * NSMP + j];
    g_dis[j] = rsqrtf(s);
}

/* ---------------- kernel 0b: transpose+convert weight ---------------- */
__global__ void k_wt(const float* __restrict__ w) {
    int i = blockIdx.x * 256 + threadIdx.x;
    if (i < NAX * DOUTC) {
        int k = i / DOUTC, c = i % DOUTC;
        g_WT[c * NAX + k] = __float2bfloat16(w[i]);
    }
}

/* ---------------- kernel 2: S' = dis ⊙ (X @ W) ---------------- */
__global__ void __launch_bounds__(256, 1) k_support(const float* __restrict__ in) {
    extern __shared__ __nv_bfloat16 sh[];
    __nv_bfloat16* sA = sh;
    __nv_bfloat16* sB = sh + 2 * 64 * ST;

    const int t    = threadIdx.x;
    const int row0 = blockIdx.x * 64;
    const int warp = t >> 5, lane = t & 31;
    const int wm = warp & 3, wn = warp >> 2;
    const int g  = lane >> 2, tq = lane & 3;
    const int lr = t >> 2, lc = (t & 3) * 8;

    float acc[16][4];
#pragma unroll
    for (int f = 0; f < 16; f++) { acc[f][0]=acc[f][1]=acc[f][2]=acc[f][3]=0.f; }

    const float* gA = in + (size_t)(row0 + lr) * NCOLS + lc;   /* X */
    const __nv_bfloat16* gB = g_WT + (size_t)t * NAX;

    float4 ra0, ra1; uint4 rb0, rb1, rb2, rb3;
    ra0 = *(const float4*)(gA);
    ra1 = *(const float4*)(gA + 4);
    rb0 = *(const uint4*)(gB);
    rb1 = *(const uint4*)(gB + 8);
    rb2 = *(const uint4*)(gB + 16);
    rb3 = *(const uint4*)(gB + 24);

    const int NKT = NAX / 32;
    for (int kt = 0; kt < NKT; ++kt) {
        __nv_bfloat16* a_s = sA + (kt & 1) * 64 * ST;
        __nv_bfloat16* b_s = sB + (kt & 1) * 256 * ST;
        uint4 ap;
        ap.x = pk_bf2(ra0.x, ra0.y); ap.y = pk_bf2(ra0.z, ra0.w);
        ap.z = pk_bf2(ra1.x, ra1.y); ap.w = pk_bf2(ra1.z, ra1.w);
        *(uint4*)(a_s + lr * ST + lc) = ap;
        *(uint4*)(b_s + t * ST +  0) = rb0;
        *(uint4*)(b_s + t * ST +  8) = rb1;
        *(uint4*)(b_s + t * ST + 16) = rb2;
        *(uint4*)(b_s + t * ST + 24) = rb3;
        __syncthreads();
        if (kt + 1 < NKT) {
            int kn = (kt + 1) * 32;
            ra0 = *(const float4*)(gA + kn);
            ra1 = *(const float4*)(gA + kn + 4);
            rb0 = *(const uint4*)(gB + kn);
            rb1 = *(const uint4*)(gB + kn + 8);
            rb2 = *(const uint4*)(gB + kn + 16);
            rb3 = *(const uint4*)(gB + kn + 24);
        }
#pragma unroll
        for (int ks = 0; ks < 2; ks++) {
            int kb = ks * 16 + 2 * tq;
            uint32_t a0 = *(const uint32_t*)(a_s + (wm*16 + g    ) * ST + kb);
            uint32_t a1 = *(const uint32_t*)(a_s + (wm*16 + g + 8) * ST + kb);
            uint32_t a2 = *(const uint32_t*)(a_s + (wm*16 + g    ) * ST + kb + 8);
            uint32_t a3 = *(const uint32_t*)(a_s + (wm*16 + g + 8) * ST + kb + 8);
#pragma unroll
            for (int f = 0; f < 16; f++) {
                int n0 = wn * 128 + f * 8;
                uint32_t b0 = *(const uint32_t*)(b_s + (n0 + g) * ST + kb);
                uint32_t b1 = *(const uint32_t*)(b_s + (n0 + g) * ST + kb + 8);
                mma16816(acc[f], a0, a1, a2, a3, b0, b1);
            }
        }
        __syncthreads();
    }

    /* epilogue: scale by dis, write g_Spf (fp32) + smem-transposed coalesced g_SpT (bf16) */
    int r1 = row0 + wm * 16 + g;
    int r2 = r1 + 8;
    int rl1 = wm * 16 + g, rl2 = rl1 + 8;
    float d1 = g_dis[r1], d2 = g_dis[r2];
    __nv_bfloat16* tr = sh;   /* reuse: [256][AST] transpose buffer, stride 72 */
#pragma unroll
    for (int f = 0; f < 16; f++) {
        int c = wn * 128 + f * 8 + 2 * tq;
        float sp0 = acc[f][0] * d1, sp1 = acc[f][1] * d1;
        float sp2 = acc[f][2] * d2, sp3 = acc[f][3] * d2;
        *(float2*)(g_Spf + (size_t)r1 * DOUTC + c) = make_float2(sp0, sp1);
        *(float2*)(g_Spf + (size_t)r2 * DOUTC + c) = make_float2(sp2, sp3);
        tr[(c    ) * AST + rl1] = __float2bfloat16(sp0);
        tr[(c + 1) * AST + rl1] = __float2bfloat16(sp1);
        tr[(c    ) * AST + rl2] = __float2bfloat16(sp2);
        tr[(c + 1) * AST + rl2] = __float2bfloat16(sp3);
    }
    __syncthreads();
    /* coalesced write: each warp covers 4 c-rows x 128B per iteration */
    int cg = lane >> 3, jc = lane & 7;
#pragma unroll
    for (int it = 0; it < 8; it++) {
        int c = it * 32 + warp * 4 + cg;
        uint4 v = *(const uint4*)(tr + (size_t)c * AST + jc * 8);
        *(uint4*)(g_SpT + (size_t)c * NSMP + row0 + jc * 8) = v;
    }
}

/* ---------------- kernel 3: out[:,0:256] = dis ⊙ (A_eff @ S') ---------------- */
__global__ void __launch_bounds__(256, 1) k_main(float* __restrict__ out) {
    extern __shared__ __nv_bfloat16 sh[];
    const int t    = threadIdx.x;
    const int row0 = blockIdx.x * 64;
    const int warp = t >> 5, lane = t & 31;
    const int wm = warp & 3, wn = warp >> 2;
    const int g  = lane >> 2, tq = lane & 3;

    uint32_t shb = (uint32_t)__cvta_generic_to_shared(sh);

    float acc[16][4];
#pragma unroll
    for (int f = 0; f < 16; f++) { acc[f][0]=acc[f][1]=acc[f][2]=acc[f][3]=0.f; }

    /* producer: A tile 64xKT (2x16B per thread), B tile 256xKT (one row = 8x16B per thread) */
    const __nv_bfloat16* ga = g_Abf + (size_t)(row0 + (t >> 2)) * NSMP + (t & 3) * 16;
    const __nv_bfloat16* gb = g_SpT + (size_t)t * NSMP;
    const uint32_t sa_off = (uint32_t)(((t >> 2) * AST + (t & 3) * 16) * 2);
    const uint32_t sb_off = (uint32_t)((A_STAGE + t * AST) * 2);

    /* consumer lane byte-offsets for ldmatrix */
    const uint32_t a_l = (uint32_t)((((wm * 16 + (lane & 7) + ((lane >> 3) & 1) * 8) * AST)
                                     + (lane >> 4) * 8) * 2);
    const uint32_t b_l = (uint32_t)((((wn * 128 + (lane & 7) + (lane >> 4) * 8) * AST)
                                     + ((lane >> 3) & 1) * 8) * 2);

    auto PREF = [&](int stg, int k0) {
        uint32_t sb = shb + (uint32_t)(stg * (STAGE_E * 2));
        cpa16(sb + sa_off,      ga + k0);
        cpa16(sb + sa_off + 16, ga + k0 + 8);
        uint32_t sbB = sb + sb_off;
        const __nv_bfloat16* gB = gb + k0;
#pragma unroll
        for (int i = 0; i < 8; i++) cpa16(sbB + i * 16, gB + i * 8);
    };

    PREF(0, 0);
    asm volatile("cp.async.commit_group;\n" ::);
    PREF(1, KT);
    asm volatile("cp.async.commit_group;\n" ::);

    const int NKT = NSMP / KT;   /* 128 */
    for (int kt = 0; kt < NKT; ++kt) {
        asm volatile("cp.async.wait_group 1;\n" ::);
        __syncthreads();

        if (kt + 2 < NKT) PREF((kt + 2) % STAGES, (kt + 2) * KT);
        asm volatile("cp.async.commit_group;\n" ::);

        uint32_t base = shb + (uint32_t)((kt % STAGES) * (STAGE_E * 2));
#pragma unroll
        for (int ks = 0; ks < 4; ks++) {
            uint32_t a0, a1, a2, a3;
            ldsm4(a0, a1, a2, a3, base + a_l + ks * 32);
#pragma unroll
            for (int nb = 0; nb < 8; nb++) {
                uint32_t b0, b1, b2, b3;
                ldsm4(b0, b1, b2, b3,
                      base + (uint32_t)(A_STAGE * 2) + b_l + (uint32_t)(nb * (16 * AST * 2)) + ks * 32);
                mma16816(acc[2 * nb],     a0, a1, a2, a3, b0, b1);
                mma16816(acc[2 * nb + 1], a0, a1, a2, a3, b2, b3);
            }
        }
    }

    /* epilogue: out[i,c] = dis[i] * (acc + S'[i,c])  (the +S' is the identity diagonal) */
    int r1 = row0 + wm * 16 + g;
    int r2 = r1 + 8;
    float d1 = g_dis[r1], d2 = g_dis[r2];
#pragma unroll
    for (int f = 0; f < 16; f++) {
        int c = wn * 128 + f * 8 + 2 * tq;
        float2 s1 = *(const float2*)(g_Spf + (size_t)r1 * DOUTC + c);
        float2 s2 = *(const float2*)(g_Spf + (size_t)r2 * DOUTC + c);
        *(float2*)(out + (size_t)r1 * OUTS + c) =
            make_float2((acc[f][0] + s1.x) * d1, (acc[f][1] + s1.y) * d1);
        *(float2*)(out + (size_t)r2 * OUTS + c) =
            make_float2((acc[f][2] + s2.x) * d2, (acc[f][3] + s2.y) * d2);
    }
}

/* ---------------- launch ---------------- */
extern "C" void kernel_launch(void* const* d_in, const int* in_sizes, int n_in,
                              void* d_out, int out_size) {
    const float* in = (const float*)d_in[0];
    const float* w  = (const float*)d_in[1];
    float* out = (float*)d_out;

    cudaFuncSetAttribute(k_support, cudaFuncAttributeMaxDynamicSharedMemorySize, SMEM_SUP);
    cudaFuncSetAttribute(k_main,    cudaFuncAttributeMaxDynamicSharedMemorySize, SMEM_MAIN);

    k_prep<<<dim3(32, 16), 256>>>(in, out);
    k_dis<<<32, 256>>>();
    k_wt<<<(NAX * DOUTC + 255) / 256, 256>>>(w);
    k_support<<<NSMP / 64, 256, SMEM_SUP>>>(in);
    k_main<<<NSMP / 64, 256, SMEM_MAIN>>>(out);
}

// round 6
// speedup vs baseline: 1.9756x; 1.1172x over previous
#include <cuda_runtime.h>
#include <cuda_bf16.h>
#include <cstdint>

#define NSMP  8192
#define NAX   512
#define DOUTC 256
#define NCOLS 8712
#define AOFF  512
#define OUTS  8448

/* ---- k_support tiling ---- */
#define ST    40
#define SMEM_SUP ((2*64*ST + 2*256*ST) * 2)
#define AST   72

/* ---- k_main tiling: BM=64, BN=128, 2 CTAs/SM ---- */
#define BM      64
#define BN      128
#define KT      64
#define STAGES  3
#define A_STG   (BM*AST)              /* elems */
#define B_STG   (BN*AST)
#define STG_E   (A_STG + B_STG)       /* 13824 elems = 27648 B */
#define SMEM_MAIN (STAGES*STG_E*2)    /* 82944 B -> 2 CTAs/SM */

/* ---------------- scratch globals ---------------- */
__device__ float          g_part[32 * NSMP];
__device__ float          g_dis[NSMP];
__device__ float          g_Spf[NSMP * DOUTC];          /* S' fp32, [j][c] */
__device__ __nv_bfloat16  g_SpT[DOUTC * NSMP];          /* S' bf16, [n][k] K-major */
__device__ __nv_bfloat16  g_WT[DOUTC * NAX];
__device__ __nv_bfloat16  g_Abf[(size_t)NSMP * NSMP];   /* A bf16, row-major */

/* ---------------- helpers ---------------- */
__device__ __forceinline__ uint32_t pk_bf2(float a, float b) {
    __nv_bfloat162 h = __floats2bfloat162_rn(a, b);
    return *reinterpret_cast<uint32_t*>(&h);
}
__device__ __forceinline__ void mma16816(float* c,
    uint32_t a0, uint32_t a1, uint32_t a2, uint32_t a3, uint32_t b0, uint32_t b1) {
    asm volatile(
        "mma.sync.aligned.m16n8k16.row.col.f32.bf16.bf16.f32 "
        "{%0,%1,%2,%3},{%4,%5,%6,%7},{%8,%9},{%0,%1,%2,%3};\n"
        : "+f"(c[0]), "+f"(c[1]), "+f"(c[2]), "+f"(c[3])
        : "r"(a0), "r"(a1), "r"(a2), "r"(a3), "r"(b0), "r"(b1));
}
__device__ __forceinline__ void ldsm4(uint32_t& r0, uint32_t& r1, uint32_t& r2, uint32_t& r3,
                                      uint32_t saddr) {
    asm volatile("ldmatrix.sync.aligned.m8n8.x4.shared.b16 {%0,%1,%2,%3},[%4];\n"
                 : "=r"(r0), "=r"(r1), "=r"(r2), "=r"(r3) : "r"(saddr));
}
__device__ __forceinline__ void cpa16(uint32_t saddr, const void* g) {
    asm volatile("cp.async.cg.shared.global [%0],[%1],16;\n" :: "r"(saddr), "l"(g));
}

/* ---------------- kernel P: fused colsum + A copy(+I) + bf16 convert ---------------- */
__global__ void k_prep(const float* __restrict__ in, float* __restrict__ out) {
    int j4 = (blockIdx.x * 256 + threadIdx.x) * 4;   /* grid.x = 8 */
    int r0 = blockIdx.y * 256;                       /* grid.y = 32 */
    const float* p = in + (size_t)r0 * NCOLS + AOFF + j4;
    float* po = out + (size_t)r0 * OUTS + 256 + j4;
    __nv_bfloat16* pb = g_Abf + (size_t)r0 * NSMP + j4;
    float4 s = make_float4(0.f, 0.f, 0.f, 0.f);
#pragma unroll 4
    for (int r = 0; r < 256; r++) {
        float4 v = *(const float4*)p;
        s.x += v.x; s.y += v.y; s.z += v.z; s.w += v.w;
        int row = r0 + r;
        float4 w = v;
        int dd = row - j4;
        if (dd == 0) w.x += 1.f; else if (dd == 1) w.y += 1.f;
        else if (dd == 2) w.z += 1.f; else if (dd == 3) w.w += 1.f;
        *(float4*)po = w;
        uint2 pk; pk.x = pk_bf2(v.x, v.y); pk.y = pk_bf2(v.z, v.w);
        *(uint2*)pb = pk;
        p += NCOLS; po += OUTS; pb += NSMP;
    }
    *(float4*)(g_part + (size_t)blockIdx.y * NSMP + j4) = s;
}

/* ---------------- kernel 1b: d^-1/2 ---------------- */
__global__ void k_dis() {
    int j = blockIdx.x * 256 + threadIdx.x;
    float s = 1.0f;
#pragma unroll
    for (int b = 0; b < 32; b++) s += g_part[b * NSMP + j];
    g_dis[j] = rsqrtf(s);
}

/* ---------------- kernel 0b: transpose+convert weight ---------------- */
__global__ void k_wt(const float* __restrict__ w) {
    int i = blockIdx.x * 256 + threadIdx.x;
    if (i < NAX * DOUTC) {
        int k = i / DOUTC, c = i % DOUTC;
        g_WT[c * NAX + k] = __float2bfloat16(w[i]);
    }
}

/* ---------------- kernel 2: S' = dis ⊙ (X @ W) ---------------- */
__global__ void __launch_bounds__(256, 1) k_support(const float* __restrict__ in) {
    extern __shared__ __nv_bfloat16 sh[];
    __nv_bfloat16* sA = sh;
    __nv_bfloat16* sB = sh + 2 * 64 * ST;

    const int t    = threadIdx.x;
    const int row0 = blockIdx.x * 64;
    const int warp = t >> 5, lane = t & 31;
    const int wm = warp & 3, wn = warp >> 2;
    const int g  = lane >> 2, tq = lane & 3;
    const int lr = t >> 2, lc = (t & 3) * 8;

    float acc[16][4];
#pragma unroll
    for (int f = 0; f < 16; f++) { acc[f][0]=acc[f][1]=acc[f][2]=acc[f][3]=0.f; }

    const float* gA = in + (size_t)(row0 + lr) * NCOLS + lc;
    const __nv_bfloat16* gB = g_WT + (size_t)t * NAX;

    float4 ra0, ra1; uint4 rb0, rb1, rb2, rb3;
    ra0 = *(const float4*)(gA);
    ra1 = *(const float4*)(gA + 4);
    rb0 = *(const uint4*)(gB);
    rb1 = *(const uint4*)(gB + 8);
    rb2 = *(const uint4*)(gB + 16);
    rb3 = *(const uint4*)(gB + 24);

    const int NKT = NAX / 32;
    for (int kt = 0; kt < NKT; ++kt) {
        __nv_bfloat16* a_s = sA + (kt & 1) * 64 * ST;
        __nv_bfloat16* b_s = sB + (kt & 1) * 256 * ST;
        uint4 ap;
        ap.x = pk_bf2(ra0.x, ra0.y); ap.y = pk_bf2(ra0.z, ra0.w);
        ap.z = pk_bf2(ra1.x, ra1.y); ap.w = pk_bf2(ra1.z, ra1.w);
        *(uint4*)(a_s + lr * ST + lc) = ap;
        *(uint4*)(b_s + t * ST +  0) = rb0;
        *(uint4*)(b_s + t * ST +  8) = rb1;
        *(uint4*)(b_s + t * ST + 16) = rb2;
        *(uint4*)(b_s + t * ST + 24) = rb3;
        __syncthreads();
        if (kt + 1 < NKT) {
            int kn = (kt + 1) * 32;
            ra0 = *(const float4*)(gA + kn);
            ra1 = *(const float4*)(gA + kn + 4);
            rb0 = *(const uint4*)(gB + kn);
            rb1 = *(const uint4*)(gB + kn + 8);
            rb2 = *(const uint4*)(gB + kn + 16);
            rb3 = *(const uint4*)(gB + kn + 24);
        }
#pragma unroll
        for (int ks = 0; ks < 2; ks++) {
            int kb = ks * 16 + 2 * tq;
            uint32_t a0 = *(const uint32_t*)(a_s + (wm*16 + g    ) * ST + kb);
            uint32_t a1 = *(const uint32_t*)(a_s + (wm*16 + g + 8) * ST + kb);
            uint32_t a2 = *(const uint32_t*)(a_s + (wm*16 + g    ) * ST + kb + 8);
            uint32_t a3 = *(const uint32_t*)(a_s + (wm*16 + g + 8) * ST + kb + 8);
#pragma unroll
            for (int f = 0; f < 16; f++) {
                int n0 = wn * 128 + f * 8;
                uint32_t b0 = *(const uint32_t*)(b_s + (n0 + g) * ST + kb);
                uint32_t b1 = *(const uint32_t*)(b_s + (n0 + g) * ST + kb + 8);
                mma16816(acc[f], a0, a1, a2, a3, b0, b1);
            }
        }
        __syncthreads();
    }

    int r1 = row0 + wm * 16 + g;
    int r2 = r1 + 8;
    int rl1 = wm * 16 + g, rl2 = rl1 + 8;
    float d1 = g_dis[r1], d2 = g_dis[r2];
    __nv_bfloat16* tr = sh;
#pragma unroll
    for (int f = 0; f < 16; f++) {
        int c = wn * 128 + f * 8 + 2 * tq;
        float sp0 = acc[f][0] * d1, sp1 = acc[f][1] * d1;
        float sp2 = acc[f][2] * d2, sp3 = acc[f][3] * d2;
        *(float2*)(g_Spf + (size_t)r1 * DOUTC + c) = make_float2(sp0, sp1);
        *(float2*)(g_Spf + (size_t)r2 * DOUTC + c) = make_float2(sp2, sp3);
        tr[(c    ) * AST + rl1] = __float2bfloat16(sp0);
        tr[(c + 1) * AST + rl1] = __float2bfloat16(sp1);
        tr[(c    ) * AST + rl2] = __float2bfloat16(sp2);
        tr[(c + 1) * AST + rl2] = __float2bfloat16(sp3);
    }
    __syncthreads();
    int cg = lane >> 3, jc = lane & 7;
#pragma unroll
    for (int it = 0; it < 8; it++) {
        int c = it * 32 + warp * 4 + cg;
        uint4 v = *(const uint4*)(tr + (size_t)c * AST + jc * 8);
        *(uint4*)(g_SpT + (size_t)c * NSMP + row0 + jc * 8) = v;
    }
}

/* ------- kernel 3: out[:, c0:c0+128] = dis ⊙ ((A+I) @ S'), 2 CTAs/SM ------- */
__global__ void __launch_bounds__(256, 2) k_main(float* __restrict__ out) {
    extern __shared__ __nv_bfloat16 sh[];
    const int t    = threadIdx.x;
    const int row0 = blockIdx.x * BM;
    const int col0 = blockIdx.y * BN;
    const int warp = t >> 5, lane = t & 31;
    const int wm = warp & 3, wn = warp >> 2;
    const int g  = lane >> 2, tq = lane & 3;

    uint32_t shb = (uint32_t)__cvta_generic_to_shared(sh);

    float acc[8][4];
#pragma unroll
    for (int f = 0; f < 8; f++) { acc[f][0]=acc[f][1]=acc[f][2]=acc[f][3]=0.f; }

    /* producer: A 64xKT (2x16B/thread), B 128xKT (4x16B/thread) */
    const __nv_bfloat16* ga = g_Abf + (size_t)(row0 + (t >> 2)) * NSMP + (t & 3) * 16;
    const __nv_bfloat16* gb = g_SpT + (size_t)(col0 + (t >> 1)) * NSMP + (t & 1) * 32;
    const uint32_t sa_off = (uint32_t)(((t >> 2) * AST + (t & 3) * 16) * 2);
    const uint32_t sb_off = (uint32_t)((A_STG + (t >> 1) * AST + (t & 1) * 32) * 2);

    /* consumer lane byte-offsets for ldmatrix */
    const uint32_t a_l = (uint32_t)((((wm * 16 + (lane & 7) + ((lane >> 3) & 1) * 8) * AST)
                                     + (lane >> 4) * 8) * 2);
    const uint32_t b_l = (uint32_t)(A_STG * 2 +
                                    (((wn * 64 + (lane & 7) + (lane >> 4) * 8) * AST)
                                     + ((lane >> 3) & 1) * 8) * 2);

    auto PREF = [&](int stg, int k0) {
        uint32_t sb = shb + (uint32_t)(stg * (STG_E * 2));
        cpa16(sb + sa_off,      ga + k0);
        cpa16(sb + sa_off + 16, ga + k0 + 8);
        uint32_t sbB = sb + sb_off;
        const __nv_bfloat16* gB = gb + k0;
#pragma unroll
        for (int i = 0; i < 4; i++) cpa16(sbB + i * 16, gB + i * 8);
    };

    PREF(0, 0);
    asm volatile("cp.async.commit_group;\n" ::);
    PREF(1, KT);
    asm volatile("cp.async.commit_group;\n" ::);

    const int NKT = NSMP / KT;   /* 128 */
    for (int kt = 0; kt < NKT; ++kt) {
        asm volatile("cp.async.wait_group 1;\n" ::);
        __syncthreads();

        if (kt + 2 < NKT) PREF((kt + 2) % STAGES, (kt + 2) * KT);
        asm volatile("cp.async.commit_group;\n" ::);

        uint32_t base = shb + (uint32_t)((kt % STAGES) * (STG_E * 2));
#pragma unroll
        for (int ks = 0; ks < 4; ks++) {
            uint32_t a0, a1, a2, a3;
            ldsm4(a0, a1, a2, a3, base + a_l + ks * 32);
#pragma unroll
            for (int nb = 0; nb < 4; nb++) {
                uint32_t b0, b1, b2, b3;
                ldsm4(b0, b1, b2, b3,
                      base + b_l + (uint32_t)(nb * (16 * AST * 2)) + ks * 32);
                mma16816(acc[2 * nb],     a0, a1, a2, a3, b0, b1);
                mma16816(acc[2 * nb + 1], a0, a1, a2, a3, b2, b3);
            }
        }
    }

    /* epilogue: out[i, col0+c] = dis[i] * (acc + S'[i, col0+c]) */
    int r1 = row0 + wm * 16 + g;
    int r2 = r1 + 8;
    float d1 = g_dis[r1], d2 = g_dis[r2];
#pragma unroll
    for (int f = 0; f < 8; f++) {
        int c = col0 + wn * 64 + (f >> 1) * 16 + (f & 1) * 8 + 2 * tq;
        float2 s1 = *(const float2*)(g_Spf + (size_t)r1 * DOUTC + c);
        float2 s2 = *(const float2*)(g_Spf + (size_t)r2 * DOUTC + c);
        *(float2*)(out + (size_t)r1 * OUTS + c) =
            make_float2((acc[f][0] + s1.x) * d1, (acc[f][1] + s1.y) * d1);
        *(float2*)(out + (size_t)r2 * OUTS + c) =
            make_float2((acc[f][2] + s2.x) * d2, (acc[f][3] + s2.y) * d2);
    }
}

/* ---------------- launch ---------------- */
extern "C" void kernel_launch(void* const* d_in, const int* in_sizes, int n_in,
                              void* d_out, int out_size) {
    const float* in = (const float*)d_in[0];
    const float* w  = (const float*)d_in[1];
    float* out = (float*)d_out;

    cudaFuncSetAttribute(k_support, cudaFuncAttributeMaxDynamicSharedMemorySize, SMEM_SUP);
    cudaFuncSetAttribute(k_main,    cudaFuncAttributeMaxDynamicSharedMemorySize, SMEM_MAIN);

    k_prep<<<dim3(8, 32), 256>>>(in, out);
    k_dis<<<32, 256>>>();
    k_wt<<<(NAX * DOUTC + 255) / 256, 256>>>(w);
    k_support<<<NSMP / 64, 256, SMEM_SUP>>>(in);
    k_main<<<dim3(NSMP / BM, DOUTC / BN), 256, SMEM_MAIN>>>(out);
}

// round 7
// speedup vs baseline: 1.9904x; 1.0075x over previous
#include <cuda_runtime.h>
#include <cuda_bf16.h>
#include <cuda_fp8.h>
#include <cstdint>

#define NSMP  8192
#define NAX   512
#define DOUTC 256
#define NCOLS 8712
#define AOFF  512
#define OUTS  8448

/* ---- k_support tiling ---- */
#define ST    40
#define SMEM_SUP ((2*64*ST + 2*256*ST) * 2)

/* ---- k_main (fp8) tiling: BM=64, BN=128, KT=128 fp8, 2 CTAs/SM ---- */
#define BM      64
#define BN      128
#define KTB     128                   /* K bytes (= fp8 elems) per stage */
#define STAGES  3
#define ASTB    144                   /* smem row stride in BYTES (128 + 16 pad) */
#define A_STGB  (BM*ASTB)             /* 9216 B */
#define B_STGB  (BN*ASTB)             /* 18432 B */
#define STG_B   (A_STGB + B_STGB)     /* 27648 B */
#define SMEM_MAIN (STAGES*STG_B)      /* 82944 B -> 2 CTAs/SM */

#define SMEM_B8 (64*260*4)            /* 66560 B */

/* ---------------- scratch globals ---------------- */
__device__ float          g_part[32 * NSMP];
__device__ float          g_dis[NSMP];
__device__ float          g_rowA[NSMP];                 /* exact row sums of A */
__device__ float          g_Spf[NSMP * DOUTC];          /* S' fp32, [j][c] */
__device__ float          g_bpart[32 * DOUTC];          /* partial col sums of S' */
__device__ float          g_beta[DOUTC];                /* col means of S' */
__device__ __nv_bfloat16  g_WT[DOUTC * NAX];
__device__ __align__(16) unsigned char g_A8[(size_t)NSMP * NSMP];  /* A e4m3 */
__device__ __align__(16) unsigned char g_B8[(size_t)DOUTC * NSMP]; /* (S'-beta)^T e4m3, [c][j] */

/* ---------------- helpers ---------------- */
__device__ __forceinline__ uint32_t pk_bf2(float a, float b) {
    __nv_bfloat162 h = __floats2bfloat162_rn(a, b);
    return *reinterpret_cast<uint32_t*>(&h);
}
__device__ __forceinline__ uint32_t pk_e4m3_4(float a, float b, float c, float d) {
    uint32_t lo = (uint32_t)__nv_cvt_float2_to_fp8x2(make_float2(a, b), __NV_SATFINITE, __NV_E4M3);
    uint32_t hi = (uint32_t)__nv_cvt_float2_to_fp8x2(make_float2(c, d), __NV_SATFINITE, __NV_E4M3);
    return lo | (hi << 16);
}
__device__ __forceinline__ void mma16816(float* c,
    uint32_t a0, uint32_t a1, uint32_t a2, uint32_t a3, uint32_t b0, uint32_t b1) {
    asm volatile(
        "mma.sync.aligned.m16n8k16.row.col.f32.bf16.bf16.f32 "
        "{%0,%1,%2,%3},{%4,%5,%6,%7},{%8,%9},{%0,%1,%2,%3};\n"
        : "+f"(c[0]), "+f"(c[1]), "+f"(c[2]), "+f"(c[3])
        : "r"(a0), "r"(a1), "r"(a2), "r"(a3), "r"(b0), "r"(b1));
}
__device__ __forceinline__ void mma16832e(float* c,
    uint32_t a0, uint32_t a1, uint32_t a2, uint32_t a3, uint32_t b0, uint32_t b1) {
    asm volatile(
        "mma.sync.aligned.m16n8k32.row.col.f32.e4m3.e4m3.f32 "
        "{%0,%1,%2,%3},{%4,%5,%6,%7},{%8,%9},{%0,%1,%2,%3};\n"
        : "+f"(c[0]), "+f"(c[1]), "+f"(c[2]), "+f"(c[3])
        : "r"(a0), "r"(a1), "r"(a2), "r"(a3), "r"(b0), "r"(b1));
}
__device__ __forceinline__ void ldsm4(uint32_t& r0, uint32_t& r1, uint32_t& r2, uint32_t& r3,
                                      uint32_t saddr) {
    asm volatile("ldmatrix.sync.aligned.m8n8.x4.shared.b16 {%0,%1,%2,%3},[%4];\n"
                 : "=r"(r0), "=r"(r1), "=r"(r2), "=r"(r3) : "r"(saddr));
}
__device__ __forceinline__ void cpa16(uint32_t saddr, const void* g) {
    asm volatile("cp.async.cg.shared.global [%0],[%1],16;\n" :: "r"(saddr), "l"(g));
}

/* ------- kernel P: fused colsum + A copy + e4m3 convert (diag fixup after loop) ------- */
__global__ void k_prep(const float* __restrict__ in, float* __restrict__ out) {
    int j4 = (blockIdx.x * 256 + threadIdx.x) * 4;   /* grid.x = 8 */
    int r0 = blockIdx.y * 256;                       /* grid.y = 32 */
    const float* p = in + (size_t)r0 * NCOLS + AOFF + j4;
    float* po = out + (size_t)r0 * OUTS + 256 + j4;
    unsigned char* pa = g_A8 + (size_t)r0 * NSMP + j4;
    float4 s = make_float4(0.f, 0.f, 0.f, 0.f);
#pragma unroll 4
    for (int r = 0; r < 256; r++) {
        float4 v = *(const float4*)p;
        s.x += v.x; s.y += v.y; s.z += v.z; s.w += v.w;
        *(float4*)po = v;
        *(uint32_t*)pa = pk_e4m3_4(v.x, v.y, v.z, v.w);
        p += NCOLS; po += OUTS; pa += NSMP;
    }
    *(float4*)(g_part + (size_t)blockIdx.y * NSMP + j4) = s;
    /* diagonal fixup: element (j, j) lies in this block iff r0 <= j < r0+256 */
#pragma unroll
    for (int k = 0; k < 4; k++) {
        int j = j4 + k;
        if (j >= r0 && j < r0 + 256)
            out[(size_t)j * OUTS + 256 + j] += 1.0f;
    }
}

/* ---------------- kernel 1b: d^-1/2 ---------------- */
__global__ void k_dis() {
    int j = blockIdx.x * 256 + threadIdx.x;
    float s = 1.0f;
#pragma unroll
    for (int b = 0; b < 32; b++) s += g_part[b * NSMP + j];
    g_dis[j] = rsqrtf(s);
}

/* ---------------- kernel R: exact row sums of A (reads A+I copy, subtract 1) ---------- */
__global__ void k_rowsum(const float* __restrict__ o) {
    int row = blockIdx.x;
    int t = threadIdx.x, lane = t & 31, w = t >> 5;
    const float* p = o + (size_t)row * OUTS + 256;
    float s = 0.f;
#pragma unroll
    for (int i = 0; i < 8; i++) {
        float4 v = *(const float4*)(p + (size_t)(i * 256 + t) * 4);
        s += (v.x + v.y) + (v.z + v.w);
    }
    s += __shfl_down_sync(0xffffffffu, s, 16);
    s += __shfl_down_sync(0xffffffffu, s, 8);
    s += __shfl_down_sync(0xffffffffu, s, 4);
    s += __shfl_down_sync(0xffffffffu, s, 2);
    s += __shfl_down_sync(0xffffffffu, s, 1);
    __shared__ float ws[8];
    if (lane == 0) ws[w] = s;
    __syncthreads();
    if (t == 0) {
        float tot = 0.f;
#pragma unroll
        for (int i = 0; i < 8; i++) tot += ws[i];
        g_rowA[row] = tot - 1.0f;   /* remove identity contribution */
    }
}

/* ---------------- kernel 0b: transpose+convert weight ---------------- */
__global__ void k_wt(const float* __restrict__ w) {
    int i = blockIdx.x * 256 + threadIdx.x;
    if (i < NAX * DOUTC) {
        int k = i / DOUTC, c = i % DOUTC;
        g_WT[c * NAX + k] = __float2bfloat16(w[i]);
    }
}

/* ---------------- kernel 2: S' = dis ⊙ (X @ W), bf16 MMA ---------------- */
__global__ void __launch_bounds__(256, 1) k_support(const float* __restrict__ in) {
    extern __shared__ __nv_bfloat16 sh[];
    __nv_bfloat16* sA = sh;
    __nv_bfloat16* sB = sh + 2 * 64 * ST;

    const int t    = threadIdx.x;
    const int row0 = blockIdx.x * 64;
    const int warp = t >> 5, lane = t & 31;
    const int wm = warp & 3, wn = warp >> 2;
    const int g  = lane >> 2, tq = lane & 3;
    const int lr = t >> 2, lc = (t & 3) * 8;

    float acc[16][4];
#pragma unroll
    for (int f = 0; f < 16; f++) { acc[f][0]=acc[f][1]=acc[f][2]=acc[f][3]=0.f; }

    const float* gA = in + (size_t)(row0 + lr) * NCOLS + lc;
    const __nv_bfloat16* gB = g_WT + (size_t)t * NAX;

    float4 ra0, ra1; uint4 rb0, rb1, rb2, rb3;
    ra0 = *(const float4*)(gA);
    ra1 = *(const float4*)(gA + 4);
    rb0 = *(const uint4*)(gB);
    rb1 = *(const uint4*)(gB + 8);
    rb2 = *(const uint4*)(gB + 16);
    rb3 = *(const uint4*)(gB + 24);

    const int NKT = NAX / 32;
    for (int kt = 0; kt < NKT; ++kt) {
        __nv_bfloat16* a_s = sA + (kt & 1) * 64 * ST;
        __nv_bfloat16* b_s = sB + (kt & 1) * 256 * ST;
        uint4 ap;
        ap.x = pk_bf2(ra0.x, ra0.y); ap.y = pk_bf2(ra0.z, ra0.w);
        ap.z = pk_bf2(ra1.x, ra1.y); ap.w = pk_bf2(ra1.z, ra1.w);
        *(uint4*)(a_s + lr * ST + lc) = ap;
        *(uint4*)(b_s + t * ST +  0) = rb0;
        *(uint4*)(b_s + t * ST +  8) = rb1;
        *(uint4*)(b_s + t * ST + 16) = rb2;
        *(uint4*)(b_s + t * ST + 24) = rb3;
        __syncthreads();
        if (kt + 1 < NKT) {
            int kn = (kt + 1) * 32;
            ra0 = *(const float4*)(gA + kn);
            ra1 = *(const float4*)(gA + kn + 4);
            rb0 = *(const uint4*)(gB + kn);
            rb1 = *(const uint4*)(gB + kn + 8);
            rb2 = *(const uint4*)(gB + kn + 16);
            rb3 = *(const uint4*)(gB + kn + 24);
        }
#pragma unroll
        for (int ks = 0; ks < 2; ks++) {
            int kb = ks * 16 + 2 * tq;
            uint32_t a0 = *(const uint32_t*)(a_s + (wm*16 + g    ) * ST + kb);
            uint32_t a1 = *(const uint32_t*)(a_s + (wm*16 + g + 8) * ST + kb);
            uint32_t a2 = *(const uint32_t*)(a_s + (wm*16 + g    ) * ST + kb + 8);
            uint32_t a3 = *(const uint32_t*)(a_s + (wm*16 + g + 8) * ST + kb + 8);
#pragma unroll
            for (int f = 0; f < 16; f++) {
                int n0 = wn * 128 + f * 8;
                uint32_t b0 = *(const uint32_t*)(b_s + (n0 + g) * ST + kb);
                uint32_t b1 = *(const uint32_t*)(b_s + (n0 + g) * ST + kb + 8);
                mma16816(acc[f], a0, a1, a2, a3, b0, b1);
            }
        }
        __syncthreads();
    }

    int r1 = row0 + wm * 16 + g;
    int r2 = r1 + 8;
    float d1 = g_dis[r1], d2 = g_dis[r2];
#pragma unroll
    for (int f = 0; f < 16; f++) {
        int c = wn * 128 + f * 8 + 2 * tq;
        *(float2*)(g_Spf + (size_t)r1 * DOUTC + c) =
            make_float2(acc[f][0] * d1, acc[f][1] * d1);
        *(float2*)(g_Spf + (size_t)r2 * DOUTC + c) =
            make_float2(acc[f][2] * d2, acc[f][3] * d2);
    }
}

/* ---------------- kernel BM: partial column sums of S' ---------------- */
__global__ void k_bmean() {
    int t = threadIdx.x, b = blockIdx.x;     /* grid 32 */
    const float* p = g_Spf + (size_t)b * 256 * DOUTC + t;
    float s = 0.f;
#pragma unroll 8
    for (int r = 0; r < 256; r++) s += p[(size_t)r * DOUTC];
    g_bpart[b * DOUTC + t] = s;
}

/* ------- kernel B8: beta + centered-fp8 B^T: g_B8[c][j] = e4m3(S'[j][c] - beta[c]) ------ */
__global__ void k_b8() {
    extern __shared__ float sm[];            /* [64][260] */
    __shared__ float sbeta[DOUTC];
    int t = threadIdx.x, b = blockIdx.x;     /* grid 128 */
    int j0 = b * 64;

    float bt = 0.f;
#pragma unroll
    for (int p = 0; p < 32; p++) bt += g_bpart[p * DOUTC + t];
    bt *= (1.0f / (float)NSMP);
    sbeta[t] = bt;
    if (b == 0) g_beta[t] = bt;
    __syncthreads();

    for (int r = 0; r < 64; r++)
        sm[r * 260 + t] = g_Spf[(size_t)(j0 + r) * DOUTC + t];
    __syncthreads();

    int q = t & 3;
#pragma unroll
    for (int it = 0; it < 4; it++) {
        int c = (t >> 2) + it * 64;
        float bc = sbeta[c];
        uint4 wv;
        uint32_t* wp = &wv.x;
#pragma unroll
        for (int wd = 0; wd < 4; wd++) {
            int jj = q * 16 + wd * 4;
            wp[wd] = pk_e4m3_4(sm[(jj + 0) * 260 + c] - bc,
                               sm[(jj + 1) * 260 + c] - bc,
                               sm[(jj + 2) * 260 + c] - bc,
                               sm[(jj + 3) * 260 + c] - bc);
        }
        *(uint4*)(g_B8 + (size_t)c * NSMP + j0 + q * 16) = wv;
    }
}

/* ------- kernel 3: fp8 GEMM: out[:, c0:c0+128] = dis ⊙ ((A+I) @ S') ------- */
__global__ void __launch_bounds__(256, 2) k_main(float* __restrict__ out) {
    extern __shared__ unsigned char sh8[];
    const int t    = threadIdx.x;
    const int row0 = blockIdx.x * BM;
    const int col0 = blockIdx.y * BN;
    const int warp = t >> 5, lane = t & 31;
    const int wm = warp & 3, wn = warp >> 2;
    const int g  = lane >> 2, tq = lane & 3;

    uint32_t shb = (uint32_t)__cvta_generic_to_shared(sh8);

    float acc[8][4];
#pragma unroll
    for (int f = 0; f < 8; f++) { acc[f][0]=acc[f][1]=acc[f][2]=acc[f][3]=0.f; }

    /* producer (bytes): A 64xKTB (2x16B/thread), B 128xKTB (4x16B/thread) */
    const unsigned char* ga = g_A8 + (size_t)(row0 + (t >> 2)) * NSMP + (t & 3) * 32;
    const unsigned char* gb = g_B8 + (size_t)(col0 + (t >> 1)) * NSMP + (t & 1) * 64;
    const uint32_t sa_off = (uint32_t)((t >> 2) * ASTB + (t & 3) * 32);
    const uint32_t sb_off = (uint32_t)(A_STGB + (t >> 1) * ASTB + (t & 1) * 64);

    /* consumer lane byte-offsets for ldmatrix (fp8-k32 frag == bf16-k16 frag as bytes) */
    const uint32_t a_l = (uint32_t)((wm * 16 + (lane & 7) + ((lane >> 3) & 1) * 8) * ASTB
                                    + (lane >> 4) * 16);
    const uint32_t b_l = (uint32_t)(A_STGB +
                                    (wn * 64 + (lane & 7) + (lane >> 4) * 8) * ASTB
                                    + ((lane >> 3) & 1) * 16);

    auto PREF = [&](int stg, int kbyte) {
        uint32_t sb = shb + (uint32_t)(stg * STG_B);
        cpa16(sb + sa_off,      ga + kbyte);
        cpa16(sb + sa_off + 16, ga + kbyte + 16);
        uint32_t sbB = sb + sb_off;
        const unsigned char* gB = gb + kbyte;
#pragma unroll
        for (int i = 0; i < 4; i++) cpa16(sbB + i * 16, gB + i * 16);
    };

    PREF(0, 0);
    asm volatile("cp.async.commit_group;\n" ::);
    PREF(1, KTB);
    asm volatile("cp.async.commit_group;\n" ::);

    const int NKT = NSMP / KTB;   /* 64 */
    for (int kt = 0; kt < NKT; ++kt) {
        asm volatile("cp.async.wait_group 1;\n" ::);
        __syncthreads();

        if (kt + 2 < NKT) PREF((kt + 2) % STAGES, (kt + 2) * KTB);
        asm volatile("cp.async.commit_group;\n" ::);

        uint32_t base = shb + (uint32_t)((kt % STAGES) * STG_B);
#pragma unroll
        for (int ks = 0; ks < 4; ks++) {
            uint32_t a0, a1, a2, a3;
            ldsm4(a0, a1, a2, a3, base + a_l + ks * 32);
#pragma unroll
            for (int nb = 0; nb < 4; nb++) {
                uint32_t b0, b1, b2, b3;
                ldsm4(b0, b1, b2, b3,
                      base + b_l + (uint32_t)(nb * (16 * ASTB)) + ks * 32);
                mma16832e(acc[2 * nb],     a0, a1, a2, a3, b0, b1);
                mma16832e(acc[2 * nb + 1], a0, a1, a2, a3, b2, b3);
            }
        }
    }

    /* epilogue: out[i,c] = dis[i]*(acc + rowA[i]*beta[c] + S'[i,c]) */
    int r1 = row0 + wm * 16 + g;
    int r2 = r1 + 8;
    float d1 = g_dis[r1], d2 = g_dis[r2];
    float ra1 = g_rowA[r1], ra2 = g_rowA[r2];
#pragma unroll
    for (int f = 0; f < 8; f++) {
        int c = col0 + wn * 64 + (f >> 1) * 16 + (f & 1) * 8 + 2 * tq;
        float2 bb = *(const float2*)(g_beta + c);
        float2 s1 = *(const float2*)(g_Spf + (size_t)r1 * DOUTC + c);
        float2 s2 = *(const float2*)(g_Spf + (size_t)r2 * DOUTC + c);
        *(float2*)(out + (size_t)r1 * OUTS + c) =
            make_float2((acc[f][0] + ra1 * bb.x + s1.x) * d1,
                        (acc[f][1] + ra1 * bb.y + s1.y) * d1);
        *(float2*)(out + (size_t)r2 * OUTS + c) =
            make_float2((acc[f][2] + ra2 * bb.x + s2.x) * d2,
                        (acc[f][3] + ra2 * bb.y + s2.y) * d2);
    }
}

/* ---------------- launch ---------------- */
extern "C" void kernel_launch(void* const* d_in, const int* in_sizes, int n_in,
                              void* d_out, int out_size) {
    const float* in = (const float*)d_in[0];
    const float* w  = (const float*)d_in[1];
    float* out = (float*)d_out;

    cudaFuncSetAttribute(k_support, cudaFuncAttributeMaxDynamicSharedMemorySize, SMEM_SUP);
    cudaFuncSetAttribute(k_main,    cudaFuncAttributeMaxDynamicSharedMemorySize, SMEM_MAIN);
    cudaFuncSetAttribute(k_b8,      cudaFuncAttributeMaxDynamicSharedMemorySize, SMEM_B8);

    k_prep<<<dim3(8, 32), 256>>>(in, out);
    k_dis<<<32, 256>>>();
    k_rowsum<<<NSMP, 256>>>(out);
    k_wt<<<(NAX * DOUTC + 255) / 256, 256>>>(w);
    k_support<<<NSMP / 64, 256, SMEM_SUP>>>(in);
    k_bmean<<<32, 256>>>();
    k_b8<<<NSMP / 64, 256, SMEM_B8>>>();
    k_main<<<dim3(NSMP / BM, DOUTC / BN), 256, SMEM_MAIN>>>(out);
}

// round 11
// speedup vs baseline: 2.2838x; 1.1474x over previous
#include <cuda_runtime.h>
#include <cuda_bf16.h>
#include <cuda_fp8.h>
#include <cstdint>

#define NSMP  8192
#define NAX   512
#define DOUTC 256
#define NCOLS 8712
#define AOFF  512
#define OUTS  8448

/* ---- shared pipeline tiling (k_support bf16 / k_main fp8): BM=64, BN=128 ---- */
#define BM      64
#define BN      128
#define STAGES  3
#define ASTB    144                   /* smem row stride in BYTES (128 + 16 pad) */
#define A_STGB  (BM*ASTB)             /* 9216 B */
#define B_STGB  (BN*ASTB)             /* 18432 B */
#define STG_B   (A_STGB + B_STGB)     /* 27648 B */
#define SMEM_PIPE (STAGES*STG_B)      /* 82944 B -> 2 CTAs/SM */

#define SMEM_B8 (64*260*4)            /* 66560 B */

/* ---------------- scratch globals ---------------- */
__device__ float          g_part[128 * NSMP];           /* colsum partials of (A-1/2) */
__device__ float          g_dis[NSMP];
__device__ float          g_Spf[NSMP * DOUTC];          /* S' fp32, [j][c] */
__device__ float          g_bpart[32 * DOUTC];          /* partial colsums of S' (fp32) */
__device__ float          g_hb[DOUTC];                  /* 0.5 * colsum(S') exact */
__device__ __nv_bfloat16  g_WT[DOUTC * NAX];            /* W^T bf16 [c][k] */
__device__ __nv_bfloat16  g_Xb[(size_t)NSMP * NAX];     /* X bf16 [m][k] */
__device__ __align__(16) unsigned char g_A8[(size_t)NSMP * NSMP];  /* fp8(A - 1/2) */
__device__ __align__(16) unsigned char g_B8[(size_t)DOUTC * NSMP]; /* fp8(S')^T [c][j] */

/* ---------------- helpers ---------------- */
__device__ __forceinline__ uint32_t pk_bf2(float a, float b) {
    __nv_bfloat162 h = __floats2bfloat162_rn(a, b);
    return *reinterpret_cast<uint32_t*>(&h);
}
__device__ __forceinline__ uint32_t pk_e4m3_4(float a, float b, float c, float d) {
    uint32_t lo = (uint32_t)__nv_cvt_float2_to_fp8x2(make_float2(a, b), __NV_SATFINITE, __NV_E4M3);
    uint32_t hi = (uint32_t)__nv_cvt_float2_to_fp8x2(make_float2(c, d), __NV_SATFINITE, __NV_E4M3);
    return lo | (hi << 16);
}
__device__ __forceinline__ void mma16816(float* c,
    uint32_t a0, uint32_t a1, uint32_t a2, uint32_t a3, uint32_t b0, uint32_t b1) {
    asm volatile(
        "mma.sync.aligned.m16n8k16.row.col.f32.bf16.bf16.f32 "
        "{%0,%1,%2,%3},{%4,%5,%6,%7},{%8,%9},{%0,%1,%2,%3};\n"
        : "+f"(c[0]), "+f"(c[1]), "+f"(c[2]), "+f"(c[3])
        : "r"(a0), "r"(a1), "r"(a2), "r"(a3), "r"(b0), "r"(b1));
}
__device__ __forceinline__ void mma16832e(float* c,
    uint32_t a0, uint32_t a1, uint32_t a2, uint32_t a3, uint32_t b0, uint32_t b1) {
    asm volatile(
        "mma.sync.aligned.m16n8k32.row.col.f32.e4m3.e4m3.f32 "
        "{%0,%1,%2,%3},{%4,%5,%6,%7},{%8,%9},{%0,%1,%2,%3};\n"
        : "+f"(c[0]), "+f"(c[1]), "+f"(c[2]), "+f"(c[3])
        : "r"(a0), "r"(a1), "r"(a2), "r"(a3), "r"(b0), "r"(b1));
}
__device__ __forceinline__ void ldsm4(uint32_t& r0, uint32_t& r1, uint32_t& r2, uint32_t& r3,
                                      uint32_t saddr) {
    asm volatile("ldmatrix.sync.aligned.m8n8.x4.shared.b16 {%0,%1,%2,%3},[%4];\n"
                 : "=r"(r0), "=r"(r1), "=r"(r2), "=r"(r3) : "r"(saddr));
}
__device__ __forceinline__ void cpa16(uint32_t saddr, const void* g) {
    asm volatile("cp.async.cg.shared.global [%0],[%1],16;\n" :: "r"(saddr), "l"(g));
}

/* ------- kernel P: colsum(A-1/2) + A copy + fp8(A-1/2), 16 cols/thread ------- */
__global__ void k_prep(const float* __restrict__ in, float* __restrict__ out) {
    int j16 = (blockIdx.x * 256 + threadIdx.x) * 16;  /* grid.x = 2 */
    int r0  = blockIdx.y * 64;                         /* grid.y = 128 */
    const float* p = in + (size_t)r0 * NCOLS + AOFF + j16;
    float* po = out + (size_t)r0 * OUTS + 256 + j16;
    unsigned char* pa = g_A8 + (size_t)r0 * NSMP + j16;

    float s[16];
#pragma unroll
    for (int k = 0; k < 16; k++) s[k] = 0.f;

#pragma unroll 2
    for (int r = 0; r < 64; r++) {
        float4 v0 = *(const float4*)(p);
        float4 v1 = *(const float4*)(p + 4);
        float4 v2 = *(const float4*)(p + 8);
        float4 v3 = *(const float4*)(p + 12);
        *(float4*)(po)      = v0;
        *(float4*)(po + 4)  = v1;
        *(float4*)(po + 8)  = v2;
        *(float4*)(po + 12) = v3;
        float a0 = v0.x - 0.5f, a1 = v0.y - 0.5f, a2 = v0.z - 0.5f, a3 = v0.w - 0.5f;
        float a4 = v1.x - 0.5f, a5 = v1.y - 0.5f, a6 = v1.z - 0.5f, a7 = v1.w - 0.5f;
        float a8 = v2.x - 0.5f, a9 = v2.y - 0.5f, aa = v2.z - 0.5f, ab = v2.w - 0.5f;
        float ac = v3.x - 0.5f, ad = v3.y - 0.5f, ae = v3.z - 0.5f, af = v3.w - 0.5f;
        s[0] += a0; s[1] += a1; s[2] += a2; s[3] += a3;
        s[4] += a4; s[5] += a5; s[6] += a6; s[7] += a7;
        s[8] += a8; s[9] += a9; s[10] += aa; s[11] += ab;
        s[12] += ac; s[13] += ad; s[14] += ae; s[15] += af;
        uint4 w;
        w.x = pk_e4m3_4(a0, a1, a2, a3);
        w.y = pk_e4m3_4(a4, a5, a6, a7);
        w.z = pk_e4m3_4(a8, a9, aa, ab);
        w.w = pk_e4m3_4(ac, ad, ae, af);
        *(uint4*)pa = w;
        p += NCOLS; po += OUTS; pa += NSMP;
    }
    float* gp = g_part + (size_t)blockIdx.y * NSMP + j16;
#pragma unroll
    for (int k = 0; k < 4; k++)
        *(float4*)(gp + k * 4) = make_float4(s[4*k], s[4*k+1], s[4*k+2], s[4*k+3]);
    /* diagonal +1 fixup on the copy (same thread wrote these elements) */
#pragma unroll
    for (int k = 0; k < 16; k++) {
        int j = j16 + k;
        if (j >= r0 && j < r0 + 64)
            out[(size_t)j * OUTS + 256 + j] += 1.0f;
    }
}

/* ---------------- kernel 1b: d^-1/2 (d = 1 + 4096 + sum of centered partials) ------- */
__global__ void k_dis() {
    int j = blockIdx.x * 256 + threadIdx.x;
    float s = 4097.0f;   /* identity (1) + re-centering (8192 * 0.5) */
    for (int b = 0; b < 128; b++) s += g_part[b * NSMP + j];
    g_dis[j] = rsqrtf(s);
}

/* ---------------- kernel 0b: transpose+convert weight ---------------- */
__global__ void k_wt(const float* __restrict__ w) {
    int i = blockIdx.x * 256 + threadIdx.x;
    if (i < NAX * DOUTC) {
        int k = i / DOUTC, c = i % DOUTC;
        g_WT[c * NAX + k] = __float2bfloat16(w[i]);
    }
}

/* ---------------- kernel Xb: X fp32 -> bf16 row-major ---------------- */
__global__ void k_xb(const float* __restrict__ in) {
    int idx = blockIdx.x * 256 + threadIdx.x;    /* grid 2048 */
    int row = idx >> 6, c8 = (idx & 63) * 8;
    const float* p = in + (size_t)row * NCOLS + c8;
    float4 a = *(const float4*)p, b = *(const float4*)(p + 4);
    uint4 w;
    w.x = pk_bf2(a.x, a.y); w.y = pk_bf2(a.z, a.w);
    w.z = pk_bf2(b.x, b.y); w.w = pk_bf2(b.z, b.w);
    *(uint4*)(g_Xb + (size_t)row * NAX + c8) = w;
}

/* ------- kernel 2: S' = dis ⊙ (X @ W), bf16 cp.async+ldmatrix pipeline ------- */
__global__ void __launch_bounds__(256, 2) k_support() {
    extern __shared__ unsigned char shp[];
    const int t    = threadIdx.x;
    const int row0 = blockIdx.x * BM;
    const int col0 = blockIdx.y * BN;
    const int warp = t >> 5, lane = t & 31;
    const int wm = warp & 3, wn = warp >> 2;
    const int g  = lane >> 2, tq = lane & 3;

    uint32_t shb = (uint32_t)__cvta_generic_to_shared(shp);

    float acc[8][4];
#pragma unroll
    for (int f = 0; f < 8; f++) { acc[f][0]=acc[f][1]=acc[f][2]=acc[f][3]=0.f; }

    const __nv_bfloat16* ga = g_Xb + (size_t)(row0 + (t >> 2)) * NAX + (t & 3) * 16;
    const __nv_bfloat16* gb = g_WT + (size_t)(col0 + (t >> 1)) * NAX + (t & 1) * 32;
    const uint32_t sa_off = (uint32_t)((t >> 2) * ASTB + (t & 3) * 32);
    const uint32_t sb_off = (uint32_t)(A_STGB + (t >> 1) * ASTB + (t & 1) * 64);

    const uint32_t a_l = (uint32_t)((wm * 16 + (lane & 7) + ((lane >> 3) & 1) * 8) * ASTB
                                    + (lane >> 4) * 16);
    const uint32_t b_l = (uint32_t)(A_STGB +
                                    (wn * 64 + (lane & 7) + (lane >> 4) * 8) * ASTB
                                    + ((lane >> 3) & 1) * 16);

    auto PREF = [&](int stg, int k0) {
        uint32_t sb = shb + (uint32_t)(stg * STG_B);
        cpa16(sb + sa_off,      ga + k0);
        cpa16(sb + sa_off + 16, ga + k0 + 8);
        uint32_t sbB = sb + sb_off;
        const __nv_bfloat16* gB = gb + k0;
#pragma unroll
        for (int i = 0; i < 4; i++) cpa16(sbB + i * 16, gB + i * 8);
    };

    PREF(0, 0);
    asm volatile("cp.async.commit_group;\n" ::);
    PREF(1, 64);
    asm volatile("cp.async.commit_group;\n" ::);

    const int NKT = NAX / 64;   /* 8 */
    for (int kt = 0; kt < NKT; ++kt) {
        asm volatile("cp.async.wait_group 1;\n" ::);
        __syncthreads();

        if (kt + 2 < NKT) PREF((kt + 2) % STAGES, (kt + 2) * 64);
        asm volatile("cp.async.commit_group;\n" ::);

        uint32_t base = shb + (uint32_t)((kt % STAGES) * STG_B);
#pragma unroll
        for (int ks = 0; ks < 4; ks++) {
            uint32_t a0, a1, a2, a3;
            ldsm4(a0, a1, a2, a3, base + a_l + ks * 32);
#pragma unroll
            for (int nb = 0; nb < 4; nb++) {
                uint32_t b0, b1, b2, b3;
                ldsm4(b0, b1, b2, b3,
                      base + b_l + (uint32_t)(nb * (16 * ASTB)) + ks * 32);
                mma16816(acc[2 * nb],     a0, a1, a2, a3, b0, b1);
                mma16816(acc[2 * nb + 1], a0, a1, a2, a3, b2, b3);
            }
        }
    }

    int r1 = row0 + wm * 16 + g;
    int r2 = r1 + 8;
    float d1 = g_dis[r1], d2 = g_dis[r2];
#pragma unroll
    for (int f = 0; f < 8; f++) {
        int c = col0 + wn * 64 + (f >> 1) * 16 + (f & 1) * 8 + 2 * tq;
        *(float2*)(g_Spf + (size_t)r1 * DOUTC + c) =
            make_float2(acc[f][0] * d1, acc[f][1] * d1);
        *(float2*)(g_Spf + (size_t)r2 * DOUTC + c) =
            make_float2(acc[f][2] * d2, acc[f][3] * d2);
    }
}

/* ------- kernel BM: partial column sums of S' (fp32, exact) ------- */
__global__ void k_bmean() {
    int t = threadIdx.x, b = blockIdx.x;     /* grid 32 */
    const float* p = g_Spf + (size_t)b * 256 * DOUTC + t;
    float s = 0.f;
#pragma unroll 8
    for (int r = 0; r < 256; r++) s += p[(size_t)r * DOUTC];
    g_bpart[b * DOUTC + t] = s;
}

/* ---------------- kernel HB: g_hb[c] = 0.5 * colsum(S')  (EXACT fp32 sum) -------- */
__global__ void k_hb() {
    int c = threadIdx.x;
    float s = 0.f;
#pragma unroll
    for (int b = 0; b < 32; b++) s += g_bpart[b * DOUTC + c];
    g_hb[c] = 0.5f * s;
}

/* ------- kernel B8: transpose S' -> fp8 [c][j] (pure quantize, no sums) ------- */
__global__ void k_b8() {
    extern __shared__ float sm[];            /* [64][260] */
    int t = threadIdx.x, b = blockIdx.x;     /* grid 128 */
    int j0 = b * 64;
    for (int r = 0; r < 64; r++)
        sm[r * 260 + t] = g_Spf[(size_t)(j0 + r) * DOUTC + t];
    __syncthreads();

    int q = t & 3;
#pragma unroll
    for (int it = 0; it < 4; it++) {
        int c = (t >> 2) + it * 64;
        uint4 wv;
        uint32_t* wp = &wv.x;
#pragma unroll
        for (int wd = 0; wd < 4; wd++) {
            int jj = q * 16 + wd * 4;
            wp[wd] = pk_e4m3_4(sm[(jj + 0) * 260 + c], sm[(jj + 1) * 260 + c],
                               sm[(jj + 2) * 260 + c], sm[(jj + 3) * 260 + c]);
        }
        *(uint4*)(g_B8 + (size_t)c * NSMP + j0 + q * 16) = wv;
    }
}

/* ------- kernel 3: fp8 GEMM: out[:, c0:c0+128] = dis ⊙ ((A+I) @ S') ------- */
__global__ void __launch_bounds__(256, 2) k_main(float* __restrict__ out) {
    extern __shared__ unsigned char sh8[];
    const int t    = threadIdx.x;
    const int row0 = blockIdx.x * BM;
    const int col0 = blockIdx.y * BN;
    const int warp = t >> 5, lane = t & 31;
    const int wm = warp & 3, wn = warp >> 2;
    const int g  = lane >> 2, tq = lane & 3;

    uint32_t shb = (uint32_t)__cvta_generic_to_shared(sh8);

    float acc[8][4];
#pragma unroll
    for (int f = 0; f < 8; f++) { acc[f][0]=acc[f][1]=acc[f][2]=acc[f][3]=0.f; }

    const unsigned char* ga = g_A8 + (size_t)(row0 + (t >> 2)) * NSMP + (t & 3) * 32;
    const unsigned char* gb = g_B8 + (size_t)(col0 + (t >> 1)) * NSMP + (t & 1) * 64;
    const uint32_t sa_off = (uint32_t)((t >> 2) * ASTB + (t & 3) * 32);
    const uint32_t sb_off = (uint32_t)(A_STGB + (t >> 1) * ASTB + (t & 1) * 64);

    const uint32_t a_l = (uint32_t)((wm * 16 + (lane & 7) + ((lane >> 3) & 1) * 8) * ASTB
                                    + (lane >> 4) * 16);
    const uint32_t b_l = (uint32_t)(A_STGB +
                                    (wn * 64 + (lane & 7) + (lane >> 4) * 8) * ASTB
                                    + ((lane >> 3) & 1) * 16);

    auto PREF = [&](int stg, int kbyte) {
        uint32_t sb = shb + (uint32_t)(stg * STG_B);
        cpa16(sb + sa_off,      ga + kbyte);
        cpa16(sb + sa_off + 16, ga + kbyte + 16);
        uint32_t sbB = sb + sb_off;
        const unsigned char* gB = gb + kbyte;
#pragma unroll
        for (int i = 0; i < 4; i++) cpa16(sbB + i * 16, gB + i * 16);
    };

    PREF(0, 0);
    asm volatile("cp.async.commit_group;\n" ::);
    PREF(1, 128);
    asm volatile("cp.async.commit_group;\n" ::);

    const int NKT = NSMP / 128;   /* 64 */
    for (int kt = 0; kt < NKT; ++kt) {
        asm volatile("cp.async.wait_group 1;\n" ::);
        __syncthreads();

        if (kt + 2 < NKT) PREF((kt + 2) % STAGES, (kt + 2) * 128);
        asm volatile("cp.async.commit_group;\n" ::);

        uint32_t base = shb + (uint32_t)((kt % STAGES) * STG_B);
#pragma unroll
        for (int ks = 0; ks < 4; ks++) {
            uint32_t a0, a1, a2, a3;
            ldsm4(a0, a1, a2, a3, base + a_l + ks * 32);
#pragma unroll
            for (int nb = 0; nb < 4; nb++) {
                uint32_t b0, b1, b2, b3;
                ldsm4(b0, b1, b2, b3,
                      base + b_l + (uint32_t)(nb * (16 * ASTB)) + ks * 32);
                mma16832e(acc[2 * nb],     a0, a1, a2, a3, b0, b1);
                mma16832e(acc[2 * nb + 1], a0, a1, a2, a3, b2, b3);
            }
        }
    }

    /* epilogue: out[i,c] = dis[i]*(acc + hb[c] + S'[i,c])
       hb = 0.5*colsum(S') exactly cancels both the A-centering and the fp8-B
       quantization bias: (A'+1/2)@S' = A'@Btilde + A'@eps_b + 0.5*colsum(S') */
    int r1 = row0 + wm * 16 + g;
    int r2 = r1 + 8;
    float d1 = g_dis[r1], d2 = g_dis[r2];
#pragma unroll
    for (int f = 0; f < 8; f++) {
        int c = col0 + wn * 64 + (f >> 1) * 16 + (f & 1) * 8 + 2 * tq;
        float2 hb = *(const float2*)(g_hb + c);
        float2 s1 = *(const float2*)(g_Spf + (size_t)r1 * DOUTC + c);
        float2 s2 = *(const float2*)(g_Spf + (size_t)r2 * DOUTC + c);
        *(float2*)(out + (size_t)r1 * OUTS + c) =
            make_float2((acc[f][0] + hb.x + s1.x) * d1,
                        (acc[f][1] + hb.y + s1.y) * d1);
        *(float2*)(out + (size_t)r2 * OUTS + c) =
            make_float2((acc[f][2] + hb.x + s2.x) * d2,
                        (acc[f][3] + hb.y + s2.y) * d2);
    }
}

/* ---------------- launch ---------------- */
extern "C" void kernel_launch(void* const* d_in, const int* in_sizes, int n_in,
                              void* d_out, int out_size) {
    const float* in = (const float*)d_in[0];
    const float* w  = (const float*)d_in[1];
    float* out = (float*)d_out;

    cudaFuncSetAttribute(k_support, cudaFuncAttributeMaxDynamicSharedMemorySize, SMEM_PIPE);
    cudaFuncSetAttribute(k_main,    cudaFuncAttributeMaxDynamicSharedMemorySize, SMEM_PIPE);
    cudaFuncSetAttribute(k_b8,      cudaFuncAttributeMaxDynamicSharedMemorySize, SMEM_B8);

    k_prep<<<dim3(2, 128), 256>>>(in, out);
    k_dis<<<32, 256>>>();
    k_wt<<<(NAX * DOUTC + 255) / 256, 256>>>(w);
    k_xb<<<NSMP * NAX / 8 / 256, 256>>>(in);
    k_support<<<dim3(NSMP / BM, DOUTC / BN), 256, SMEM_PIPE>>>();
    k_bmean<<<32, 256>>>();
    k_hb<<<1, 256>>>();
    k_b8<<<NSMP / 64, 256, SMEM_B8>>>();
    k_main<<<dim3(NSMP / BM, DOUTC / BN), 256, SMEM_PIPE>>>(out);
}